// round 2
// baseline (speedup 1.0000x reference)
#include <cuda_runtime.h>
#include <cuda_bf16.h>

// GAT layer, fully fused, fp32 CUDA-core version with packed f32x2 FMA.
//   h = X @ W                       (8192x512 @ 512x128)
//   s1 = h@a1, s2 = h@a2 ; E=exp(s), F=exp(0.2 s)   (separable leaky-relu-exp)
//   w_ij = adj ? (s1_i+s2_j>0 ? E1_i*E2_j : F1_i*F2_j) : 0   (no max-shift needed)
//   out_i = elu( (sum_j w_ij h_j) / (sum_j w_ij) )

typedef unsigned long long ull;

#define FMA2(acc, a, b) asm("fma.rn.f32x2 %0, %1, %2, %0;" : "+l"(acc) : "l"(a), "l"(b))
#define PACK2(d, s)     asm("mov.b64 %0, {%1, %1};" : "=l"(d) : "f"(s))
#define UNPACK2(lo, hi, s) asm("mov.b64 {%0, %1}, %2;" : "=f"(lo), "=f"(hi) : "l"(s))

constexpr int N    = 8192;
constexpr int FIN  = 512;
constexpr int FOUT = 128;
constexpr int TI   = 32;   // i-rows per CTA in aggregation kernel
constexpr int JB   = 32;   // j-chunk

__device__ float g_h[N * FOUT];
__device__ float g_s1[N], g_s2[N];
__device__ float g_E1[N], g_F1[N], g_E2[N], g_F2[N];

// ---------------------------------------------------------------------------
// Kernel A: h = X @ W   (BM=64, BN=128(full), BK=32), f32x2 packed FMA
// ---------------------------------------------------------------------------
__global__ void __launch_bounds__(256) k_gemm_hw(const float* __restrict__ X,
                                                 const float* __restrict__ W) {
    __shared__ float sX[64][32];    // 8KB
    __shared__ float sB[32][FOUT];  // 16KB
    const int t = threadIdx.x;
    const int tx = t & 31, ty = t >> 5;   // tx -> 4 cols, ty+8k -> 8 rows
    const int m0 = blockIdx.x * 64;

    const int xr = t >> 2, xc0 = (t & 3) * 8;
    const int wr = t >> 3, wc0 = (t & 7) * 16;

    ull acc[8][2] = {};

    for (int kc = 0; kc < FIN / 32; ++kc) {
        const int k0 = kc * 32;
        __syncthreads();
        {
            float4*       dx = reinterpret_cast<float4*>(&sX[xr][xc0]);
            const float4* sx = reinterpret_cast<const float4*>(X + (size_t)(m0 + xr) * FIN + k0 + xc0);
            dx[0] = sx[0]; dx[1] = sx[1];
            float4*       dw = reinterpret_cast<float4*>(&sB[wr][wc0]);
            const float4* sw = reinterpret_cast<const float4*>(W + (size_t)(k0 + wr) * FOUT + wc0);
            dw[0] = sw[0]; dw[1] = sw[1]; dw[2] = sw[2]; dw[3] = sw[3];
        }
        __syncthreads();
        #pragma unroll 8
        for (int kk = 0; kk < 32; ++kk) {
            ulonglong2 b2 = *reinterpret_cast<const ulonglong2*>(&sB[kk][tx << 2]);
            #pragma unroll
            for (int k = 0; k < 8; ++k) {
                ull ap;
                PACK2(ap, sX[ty + 8 * k][kk]);
                FMA2(acc[k][0], ap, b2.x);
                FMA2(acc[k][1], ap, b2.y);
            }
        }
    }
    #pragma unroll
    for (int k = 0; k < 8; ++k) {
        const int r = m0 + ty + 8 * k;
        float4 o;
        UNPACK2(o.x, o.y, acc[k][0]);
        UNPACK2(o.z, o.w, acc[k][1]);
        reinterpret_cast<float4*>(g_h + (size_t)r * FOUT)[tx] = o;
    }
}

// ---------------------------------------------------------------------------
// Kernel B: s1, s2 and the four exp vectors. One block (128 thr) per row.
// ---------------------------------------------------------------------------
__global__ void __launch_bounds__(128) k_scores(const float* __restrict__ a) {
    const int i = blockIdx.x;
    const int t = threadIdx.x;
    const float hv = g_h[(size_t)i * FOUT + t];
    float p1 = hv * __ldg(&a[t]);
    float p2 = hv * __ldg(&a[FOUT + t]);
    #pragma unroll
    for (int off = 16; off; off >>= 1) {
        p1 += __shfl_xor_sync(0xffffffffu, p1, off);
        p2 += __shfl_xor_sync(0xffffffffu, p2, off);
    }
    __shared__ float r1[4], r2[4];
    const int w = t >> 5;
    if ((t & 31) == 0) { r1[w] = p1; r2[w] = p2; }
    __syncthreads();
    if (t == 0) {
        const float s1 = r1[0] + r1[1] + r1[2] + r1[3];
        const float s2 = r2[0] + r2[1] + r2[2] + r2[3];
        g_s1[i] = s1;  g_s2[i] = s2;
        g_E1[i] = __expf(s1);        g_F1[i] = __expf(0.2f * s1);
        g_E2[i] = __expf(s2);        g_F2[i] = __expf(0.2f * s2);
    }
}

// ---------------------------------------------------------------------------
// Kernel C: fused masked softmax + weighted sum + elu.
// CTA: 32 i-rows x all 8192 j. 256 threads. Per thread: 4 rows x 4 cols accum.
// ---------------------------------------------------------------------------
__device__ __forceinline__ float elu_f(float v) { return v > 0.f ? v : expm1f(v); }

__global__ void __launch_bounds__(256, 2) k_gat_agg(const int* __restrict__ adj,
                                                    float* __restrict__ out) {
    __shared__ float sH[JB][FOUT];   // 16KB h tile
    __shared__ float sW[TI][JB];     // 4KB weight tile
    __shared__ float sS1[TI], sE1[TI], sF1[TI], sDen[TI];

    const int t = threadIdx.x;
    const int tx = t & 31, ty = t >> 5;       // tx -> f group (4 cols), jj lane; ty -> row group
    const int i0 = blockIdx.x * TI;

    if (t < TI) {
        sS1[t] = g_s1[i0 + t];
        sE1[t] = g_E1[i0 + t];
        sF1[t] = g_F1[i0 + t];
    }

    ull acc[4][2] = {};
    float dpart[4] = {0.f, 0.f, 0.f, 0.f};

    const int hr = t >> 3, hc = (t & 7) << 4;  // h-tile loader mapping

    for (int c = 0; c < N / JB; ++c) {
        const int j0 = c * JB;
        __syncthreads();
        // --- stage h tile (from L2-resident g_h) ---
        {
            const float4* hp = reinterpret_cast<const float4*>(g_h + (size_t)(j0 + hr) * FOUT + hc);
            float4*       sp = reinterpret_cast<float4*>(&sH[hr][hc]);
            sp[0] = hp[0]; sp[1] = hp[1]; sp[2] = hp[2]; sp[3] = hp[3];
        }
        // --- compute weights for 32x32 pairs; fold denominator partials ---
        {
            const float s2j = g_s2[j0 + tx];
            const float e2  = g_E2[j0 + tx];
            const float f2  = g_F2[j0 + tx];
            #pragma unroll
            for (int p = 0; p < 4; ++p) {
                const int il = ty + 8 * p;
                const int av = __ldg(&adj[(i0 + il) * N + j0 + tx]);
                const float x = sS1[il] + s2j;
                float w = (x > 0.f) ? sE1[il] * e2 : sF1[il] * f2;
                w = av ? w : 0.f;
                sW[il][tx] = w;
                dpart[p] += w;
            }
        }
        __syncthreads();
        // --- rank-1 accumulate: acc[r][f] += w[r][jj] * h[jj][f] ---
        #pragma unroll 8
        for (int jj = 0; jj < JB; ++jj) {
            ulonglong2 h2 = *reinterpret_cast<const ulonglong2*>(&sH[jj][tx << 2]);
            #pragma unroll
            for (int k = 0; k < 4; ++k) {
                ull wp;
                PACK2(wp, sW[ty + 8 * k][jj]);
                FMA2(acc[k][0], wp, h2.x);
                FMA2(acc[k][1], wp, h2.y);
            }
        }
    }

    // --- denominators: lanes of warp ty hold partials over jj for rows ty+8p ---
    #pragma unroll
    for (int p = 0; p < 4; ++p) {
        float v = dpart[p];
        #pragma unroll
        for (int off = 16; off; off >>= 1) v += __shfl_xor_sync(0xffffffffu, v, off);
        if (tx == 0) sDen[ty + 8 * p] = v;
    }
    __syncthreads();

    // --- normalize + elu + store ---
    #pragma unroll
    for (int k = 0; k < 4; ++k) {
        const int r = ty + 8 * k;
        const float inv = 1.f / sDen[r];
        float4 o;
        float lo, hi;
        UNPACK2(lo, hi, acc[k][0]);
        o.x = elu_f(lo * inv); o.y = elu_f(hi * inv);
        UNPACK2(lo, hi, acc[k][1]);
        o.z = elu_f(lo * inv); o.w = elu_f(hi * inv);
        reinterpret_cast<float4*>(out + (size_t)(i0 + r) * FOUT)[tx] = o;
    }
}

// ---------------------------------------------------------------------------
extern "C" void kernel_launch(void* const* d_in, const int* in_sizes, int n_in,
                              void* d_out, int out_size) {
    const float* X   = (const float*)d_in[0];   // 8192 x 512
    const int*   adj = (const int*)  d_in[1];   // 8192 x 8192
    const float* W   = (const float*)d_in[2];   // 512 x 128
    const float* a   = (const float*)d_in[3];   // 256 x 1
    float*       out = (float*)d_out;           // 8192 x 128

    k_gemm_hw<<<N / 64, 256>>>(X, W);
    k_scores<<<N, 128>>>(a);
    k_gat_agg<<<N / TI, 256>>>(adj, out);
}

// round 4
// speedup vs baseline: 2.3243x; 2.3243x over previous
#include <cuda_runtime.h>
#include <cuda_bf16.h>
#include <cstdint>
#include <math.h>

typedef unsigned long long ull;

#define FMA2(acc, a, b) asm("fma.rn.f32x2 %0, %1, %2, %0;" : "+l"(acc) : "l"(a), "l"(b))
#define PACK2(d, s)     asm("mov.b64 %0, {%1, %1};" : "=l"(d) : "f"(s))
#define UNPACK2(lo, hi, s) asm("mov.b64 {%0, %1}, %2;" : "=f"(lo), "=f"(hi) : "l"(s))

constexpr int N    = 8192;
constexpr int FIN  = 512;
constexpr int FOUT = 128;
constexpr int NQ   = 512;    // number of k16 chunks (8192/16)

__device__ float  g_h[N * FOUT];
__device__ float4 g_hTf4[NQ * 16 * 4 * 8];   // B-fragment-ordered tf32 h^T (4MB)
__device__ float  g_E1[N], g_F1[N], g_E2[N], g_F2[N];

__device__ __forceinline__ float to_tf32(float x) {
    float r; asm("cvt.rna.tf32.f32 %0, %1;" : "=f"(r) : "f"(x)); return r;
}

// m16n8k8 tf32 warp MMA (sm_80+ PTX, works on base sm_103 target)
__device__ __forceinline__ void mma8(float* c, float a0, float a1, float a2, float a3,
                                     float b0, float b1) {
    asm volatile(
        "mma.sync.aligned.m16n8k8.row.col.f32.tf32.tf32.f32 "
        "{%0,%1,%2,%3}, {%4,%5,%6,%7}, {%8,%9}, {%0,%1,%2,%3};"
        : "+f"(c[0]), "+f"(c[1]), "+f"(c[2]), "+f"(c[3])
        : "r"(__float_as_uint(a0)), "r"(__float_as_uint(a1)),
          "r"(__float_as_uint(a2)), "r"(__float_as_uint(a3)),
          "r"(__float_as_uint(b0)), "r"(__float_as_uint(b1)));
}

__device__ __forceinline__ float elu_f(float v) { return v > 0.f ? v : expm1f(v); }

// ---------------------------------------------------------------------------
// Kernel A: h = X @ W  (fp32, packed f32x2 FMA), BM=32, grid 256.
// Also emits g_hTf4: tf32(h) in exact B-fragment order for the agg MMA.
//   j = 16q + 4lc + p  ->  float4 element p at index ((q*16+ntile)*4+lc)*8+ln
// ---------------------------------------------------------------------------
__global__ void __launch_bounds__(256) k_gemm_hw(const float* __restrict__ X,
                                                 const float* __restrict__ W) {
    __shared__ float sX[32][32];    // 4KB
    __shared__ float sB[32][FOUT];  // 16KB
    const int t = threadIdx.x;
    const int tx = t & 31, ty = t >> 5;       // tx: 4 cols, ty+8k: 4 rows
    const int m0 = blockIdx.x * 32;
    const int xr = t >> 3, xc0 = (t & 7) * 4;
    const int wr = t >> 3, wc0 = (t & 7) * 16;

    ull acc[4][2] = {};
    for (int kc = 0; kc < FIN / 32; ++kc) {
        const int k0 = kc * 32;
        __syncthreads();
        {
            float4*       dx = reinterpret_cast<float4*>(&sX[xr][xc0]);
            const float4* sx = reinterpret_cast<const float4*>(X + (size_t)(m0 + xr) * FIN + k0 + xc0);
            dx[0] = sx[0];
            float4*       dw = reinterpret_cast<float4*>(&sB[wr][wc0]);
            const float4* sw = reinterpret_cast<const float4*>(W + (size_t)(k0 + wr) * FOUT + wc0);
            dw[0] = sw[0]; dw[1] = sw[1]; dw[2] = sw[2]; dw[3] = sw[3];
        }
        __syncthreads();
        #pragma unroll 8
        for (int kk = 0; kk < 32; ++kk) {
            ulonglong2 b2 = *reinterpret_cast<const ulonglong2*>(&sB[kk][tx << 2]);
            #pragma unroll
            for (int k = 0; k < 4; ++k) {
                ull ap; PACK2(ap, sX[ty + 8 * k][kk]);
                FMA2(acc[k][0], ap, b2.x);
                FMA2(acc[k][1], ap, b2.y);
            }
        }
    }
    float* hTf = reinterpret_cast<float*>(g_hTf4);
    #pragma unroll
    for (int k = 0; k < 4; ++k) {
        const int r = m0 + ty + 8 * k;        // = j index for the agg GEMM
        float4 o;
        UNPACK2(o.x, o.y, acc[k][0]);
        UNPACK2(o.z, o.w, acc[k][1]);
        reinterpret_cast<float4*>(g_h + (size_t)r * FOUT)[tx] = o;
        const int q  = r >> 4;
        const int lc = (r >> 2) & 3;
        const int p  = r & 3;
        const float v[4] = {o.x, o.y, o.z, o.w};
        #pragma unroll
        for (int c = 0; c < 4; ++c) {
            const int f = tx * 4 + c;
            const int base = ((q * 16 + (f >> 3)) * 4 + lc) * 8 + (f & 7);
            hTf[base * 4 + p] = to_tf32(v[c]);
        }
    }
}

// ---------------------------------------------------------------------------
// Kernel B: E/F exp vectors from s = h@a1, h@a2
// ---------------------------------------------------------------------------
__global__ void __launch_bounds__(128) k_scores(const float* __restrict__ a) {
    const int i = blockIdx.x;
    const int t = threadIdx.x;
    const float hv = g_h[(size_t)i * FOUT + t];
    float p1 = hv * __ldg(&a[t]);
    float p2 = hv * __ldg(&a[FOUT + t]);
    #pragma unroll
    for (int off = 16; off; off >>= 1) {
        p1 += __shfl_xor_sync(0xffffffffu, p1, off);
        p2 += __shfl_xor_sync(0xffffffffu, p2, off);
    }
    __shared__ float r1[4], r2[4];
    const int w = t >> 5;
    if ((t & 31) == 0) { r1[w] = p1; r2[w] = p2; }
    __syncthreads();
    if (t == 0) {
        const float s1 = r1[0] + r1[1] + r1[2] + r1[3];
        const float s2 = r2[0] + r2[1] + r2[2] + r2[3];
        g_E1[i] = __expf(s1);  g_F1[i] = __expf(0.2f * s1);
        g_E2[i] = __expf(s2);  g_F2[i] = __expf(0.2f * s2);
    }
}

// ---------------------------------------------------------------------------
// Kernel C: masked-softmax aggregation as tf32 warp-MMA GEMM.
// grid 128 x (64 rows). 8 warps: 2(M) x 4(N); warp tile 32x32.
// Weights built in-register in A-fragment layout; w = adj ? max(E1E2, F1F2) : 0.
// Denominator = extra ones-column MMA on nw==3 warps (exact softmax cancel).
// ---------------------------------------------------------------------------
__global__ void __launch_bounds__(256, 1) k_agg(const int* __restrict__ adj,
                                                float* __restrict__ out) {
    extern __shared__ float sEF[];      // [0,8192) = E2, [8192,16384) = F2
    __shared__ float sDen[64];

    const int t = threadIdx.x;
    const int lane = t & 31, wid = t >> 5;
    const int mw = wid >> 2, nw = wid & 3;
    const int lr = lane >> 2, lc = lane & 3;
    const int i0 = blockIdx.x * 64;

    for (int k = t; k < N; k += 256) {
        sEF[k]     = g_E2[k];
        sEF[N + k] = g_F2[k];
    }
    __syncthreads();

    float e1[4], f1[4];
    const int4* arow[4];
    #pragma unroll
    for (int k = 0; k < 4; ++k) {
        const int row = i0 + mw * 32 + lr + 8 * k;   // rows lr, lr+8 (tile0), lr+16, lr+24 (tile1)
        e1[k] = g_E1[row];
        f1[k] = g_F1[row];
        arow[k] = reinterpret_cast<const int4*>(adj + (size_t)row * N);
    }
    const float4* sE4 = reinterpret_cast<const float4*>(sEF);
    const float4* sF4 = reinterpret_cast<const float4*>(sEF + N);

    float acc[2][4][4];                 // [mtile][ntile][reg]
    #pragma unroll
    for (int mt = 0; mt < 2; ++mt)
        #pragma unroll
        for (int nt = 0; nt < 4; ++nt)
            #pragma unroll
            for (int r = 0; r < 4; ++r) acc[mt][nt][r] = 0.f;
    float den[2][4] = {};               // nw==3 only
    const float ob = (lr == 0) ? 1.0f : 0.0f;   // ones-column B fragment (col 0)

    // prefetch buffers
    int4 a4n[4]; float4 b4n[4]; float4 e4n, f4n;
    {
        #pragma unroll
        for (int k = 0; k < 4; ++k) a4n[k] = __ldg(&arow[k][lc]);
        #pragma unroll
        for (int nt = 0; nt < 4; ++nt)
            b4n[nt] = __ldg(&g_hTf4[((nw * 4 + nt) * 4 + lc) * 8 + lr]);
        e4n = sE4[lc]; f4n = sF4[lc];
    }

    #pragma unroll 1
    for (int q = 0; q < NQ; ++q) {
        int4 a4[4]; float4 b4[4];
        const float4 e4 = e4n, f4 = f4n;
        #pragma unroll
        for (int k = 0; k < 4; ++k) a4[k] = a4n[k];
        #pragma unroll
        for (int nt = 0; nt < 4; ++nt) b4[nt] = b4n[nt];
        if (q + 1 < NQ) {
            const int qi = q + 1;
            #pragma unroll
            for (int k = 0; k < 4; ++k) a4n[k] = __ldg(&arow[k][qi * 4 + lc]);
            #pragma unroll
            for (int nt = 0; nt < 4; ++nt)
                b4n[nt] = __ldg(&g_hTf4[((qi * 16 + nw * 4 + nt) * 4 + lc) * 8 + lr]);
            e4n = sE4[qi * 4 + lc]; f4n = sF4[qi * 4 + lc];
        }

        // weights w[k][p]: row (lr + 8k within warp-M), j = 16q + 4lc + p
        float w[4][4];
        #pragma unroll
        for (int k = 0; k < 4; ++k) {
            const float ek = e1[k], fk = f1[k];
            w[k][0] = a4[k].x ? fmaxf(ek * e4.x, fk * f4.x) : 0.f;
            w[k][1] = a4[k].y ? fmaxf(ek * e4.y, fk * f4.y) : 0.f;
            w[k][2] = a4[k].z ? fmaxf(ek * e4.z, fk * f4.z) : 0.f;
            w[k][3] = a4[k].w ? fmaxf(ek * e4.w, fk * f4.w) : 0.f;
        }

        // k-step 0: j pair (p=0, p=1)
        #pragma unroll
        for (int mt = 0; mt < 2; ++mt) {
            const float a0 = w[2 * mt][0], a1 = w[2 * mt + 1][0];
            const float a2 = w[2 * mt][1], a3 = w[2 * mt + 1][1];
            #pragma unroll
            for (int nt = 0; nt < 4; ++nt)
                mma8(acc[mt][nt], a0, a1, a2, a3, b4[nt].x, b4[nt].y);
            if (nw == 3) mma8(den[mt], a0, a1, a2, a3, ob, ob);
        }
        // k-step 1: j pair (p=2, p=3)
        #pragma unroll
        for (int mt = 0; mt < 2; ++mt) {
            const float a0 = w[2 * mt][2], a1 = w[2 * mt + 1][2];
            const float a2 = w[2 * mt][3], a3 = w[2 * mt + 1][3];
            #pragma unroll
            for (int nt = 0; nt < 4; ++nt)
                mma8(acc[mt][nt], a0, a1, a2, a3, b4[nt].z, b4[nt].w);
            if (nw == 3) mma8(den[mt], a0, a1, a2, a3, ob, ob);
        }
    }

    // denominator lives in col 0 of den frags (lanes with lc==0)
    if (nw == 3 && lc == 0) {
        sDen[mw * 32 + lr]      = den[0][0];
        sDen[mw * 32 + lr + 8]  = den[0][2];
        sDen[mw * 32 + lr + 16] = den[1][0];
        sDen[mw * 32 + lr + 24] = den[1][2];
    }
    __syncthreads();

    #pragma unroll
    for (int mt = 0; mt < 2; ++mt) {
        const int r0 = mw * 32 + mt * 16 + lr;
        const float inv0 = 1.f / sDen[r0];
        const float inv1 = 1.f / sDen[r0 + 8];
        #pragma unroll
        for (int nt = 0; nt < 4; ++nt) {
            const int col = nw * 32 + nt * 8 + lc * 2;
            float2 v0, v1;
            v0.x = elu_f(acc[mt][nt][0] * inv0);
            v0.y = elu_f(acc[mt][nt][1] * inv0);
            v1.x = elu_f(acc[mt][nt][2] * inv1);
            v1.y = elu_f(acc[mt][nt][3] * inv1);
            *reinterpret_cast<float2*>(out + (size_t)(i0 + r0) * FOUT + col)     = v0;
            *reinterpret_cast<float2*>(out + (size_t)(i0 + r0 + 8) * FOUT + col) = v1;
        }
    }
}

// ---------------------------------------------------------------------------
extern "C" void kernel_launch(void* const* d_in, const int* in_sizes, int n_in,
                              void* d_out, int out_size) {
    const float* X   = (const float*)d_in[0];   // 8192 x 512
    const int*   adj = (const int*)  d_in[1];   // 8192 x 8192
    const float* W   = (const float*)d_in[2];   // 512 x 128
    const float* a   = (const float*)d_in[3];   // 256 x 1
    float*       out = (float*)d_out;           // 8192 x 128

    cudaFuncSetAttribute(k_agg, cudaFuncAttributeMaxDynamicSharedMemorySize, 65536);

    k_gemm_hw<<<N / 32, 256>>>(X, W);
    k_scores<<<N, 128>>>(a);
    k_agg<<<N / 64, 256, 65536>>>(adj, out);
}